// round 2
// baseline (speedup 1.0000x reference)
#include <cuda_runtime.h>
#include <cuda_bf16.h>
#include <math.h>

#define T_LEN 88200
#define NB 8
#define TC 1378
#define IN_GAIN 1.8197008586099834f
#define ABOVE_SLOPE 0.98500749625187401f
#define BELOW_SLOPE 0.76019184652277820f

// ---------------- scratch (device globals; no allocation allowed) ----------
__device__ float g_mh[NB * 2 * T_LEN];
__device__ float g_bands[NB * 3 * 2 * T_LEN];     // [b][band][c][t], band0=high,1=mid,2=low
__device__ float g_xrms[24 * TC];
__device__ float g_env[24 * TC];
__device__ float g_comb[NB * 2 * T_LEN];
__device__ float g_act0[NB * 64 * T_LEN];
__device__ float g_act1[NB * 64 * T_LEN];
__device__ float g_wt[3 * 12288];                 // transposed conv weights [l][(ic*3+k)*64+oc]

__device__ __forceinline__ float gelu_exact(float x) { return x * normcdff(x); }

__device__ __forceinline__ float knee_fn(float x, float thr, float slope, float k) {
    float diff = x - thr;
    float kh = 0.5f * k;
    if (fabsf(diff) <= kh) { float u = diff + kh; return slope * u * u / (2.0f * k); }
    return diff > kh ? slope * diff : 0.0f;
}

// ---------------- FIR crossover (two cascaded stages, 2 filters each) ------
// y[t] = sum_{j=0}^{511} w[j] * x[t-511+j]   (w already time-flipped by setup)
template <int STAGE>
__global__ void __launch_bounds__(256) fir_kernel(
    const float* __restrict__ in, const float* __restrict__ wA,
    const float* __restrict__ wB, float* __restrict__ bands, float* __restrict__ mh)
{
    __shared__ float swa[512], swb[512], sx[1024 + 511];
    const int row = blockIdx.y;              // b*2+c
    const int b = row >> 1, c = row & 1;
    const int t0 = blockIdx.x * 1024;
    const int tid = threadIdx.x;

    for (int i = tid; i < 512; i += 256) { swa[i] = wA[i]; swb[i] = wB[i]; }

    const float gain = (STAGE == 1) ? IN_GAIN : 1.0f;
    const float* xin = (STAGE == 1) ? (in + row * T_LEN) : (mh + row * T_LEN);
    for (int i = tid; i < 1535; i += 256) {
        int g = t0 - 511 + i;
        sx[i] = (g >= 0 && g < T_LEN) ? xin[g] * gain : 0.0f;
    }
    __syncthreads();

    float accA[4] = {0.f, 0.f, 0.f, 0.f};
    float accB[4] = {0.f, 0.f, 0.f, 0.f};
    #pragma unroll 4
    for (int k = 0; k < 512; k++) {
        float wa = swa[k], wb = swb[k];
        #pragma unroll
        for (int j = 0; j < 4; j++) {
            float xv = sx[tid + j * 256 + k];
            accA[j] = fmaf(wa, xv, accA[j]);
            accB[j] = fmaf(wb, xv, accB[j]);
        }
    }

    float* outA;
    float* outB;
    if (STAGE == 1) {       // A = lowpass -> band 2 (low); B = highpass -> m_h
        outA = bands + ((size_t)(b * 3 + 2) * 2 + c) * T_LEN;
        outB = mh + (size_t)row * T_LEN;
    } else {                // A = lowpass of m_h -> band 1 (mid); B = band 0 (high)
        outA = bands + ((size_t)(b * 3 + 1) * 2 + c) * T_LEN;
        outB = bands + ((size_t)(b * 3 + 0) * 2 + c) * T_LEN;
    }
    #pragma unroll
    for (int j = 0; j < 4; j++) {
        int t = t0 + tid + j * 256;
        if (t < T_LEN) { outA[t] = accA[j]; outB[t] = accB[j]; }
    }
}

// ---------------- per-band RMS (DS=64, mean over 2 ch) ---------------------
__global__ void xrms_kernel(const float* __restrict__ bands, float* __restrict__ xrms)
{
    const int row = blockIdx.x;                         // 0..23 = b*3+band
    const int warp = threadIdx.x >> 5, lane = threadIdx.x & 31;
    const int j = blockIdx.y * 8 + warp;
    if (j >= TC) return;
    const float* p0 = bands + (size_t)row * 2 * T_LEN;
    const float* p1 = p0 + T_LEN;
    int base = j * 64;
    float v0 = p0[base + lane], v1 = p0[base + lane + 32];
    float u0 = p1[base + lane], u1 = p1[base + lane + 32];
    float s = v0 * v0 + v1 * v1 + u0 * u0 + u1 * u1;
    #pragma unroll
    for (int o = 16; o > 0; o >>= 1) s += __shfl_xor_sync(0xffffffffu, s, o);
    if (lane == 0) xrms[row * TC + j] = sqrtf(s * (1.0f / 128.0f) + 1e-7f);
}

// ---------------- release envelope (e[n] = max(x, k*e[n-1])) ---------------
__global__ void env_kernel(const float* __restrict__ xrms,
                           const float* __restrict__ rel_alphas, float* __restrict__ env)
{
    int r = threadIdx.x;
    if (r >= 24) return;
    // replicate reference quirk: rel repeated band-major over batch-major rows -> rel[r/8]
    float kk = 1.0f - rel_alphas[r >> 3];
    const float* x = xrms + r * TC;
    float* e = env + r * TC;
    float ev = 0.0f;
    for (int n = 0; n < TC; n++) { ev = fmaxf(x[n], kk * ev); e[n] = ev; }
}

// ---------------- gain computation + band combine --------------------------
__global__ void combine_kernel(const float* __restrict__ bands, const float* __restrict__ env,
                               const float* __restrict__ params, const float* __restrict__ knee_db,
                               float* __restrict__ comb)
{
    const int t = blockIdx.x * 256 + threadIdx.x;
    const int b = blockIdx.y;
    if (t >= T_LEN) return;
    const float* pp = params + b * 7;
    const float knee = *knee_db;

    float pos = (float)t * (1377.0f / 88199.0f);
    int i0 = (int)floorf(pos);
    if (i0 > TC - 2) i0 = TC - 2;
    if (i0 < 0) i0 = 0;
    float frac = pos - (float)i0;

    float acc0 = 0.f, acc1 = 0.f;
    #pragma unroll
    for (int band = 0; band < 3; band++) {
        int r = b * 3 + band;
        float e0 = env[r * TC + i0], e1 = env[r * TC + i0 + 1];
        float e = e0 * (1.0f - frac) + e1 * frac;
        float edb = 20.0f * log10f(e + 1e-7f);
        float ta = pp[3 - band];
        float tb = pp[6 - band];
        float sa = (band == 0) ? 1.0f : ABOVE_SLOPE;
        float gdb = -knee_fn(edb, ta, sa, knee) + knee_fn(-edb, -tb, BELOW_SLOPE, knee);
        float og = (band == 1) ? 5.7f : 10.3f;
        float v = fminf(fmaxf(gdb + og, -80.0f), 40.0f);
        float g = exp10f(v * 0.05f);
        const float* bb = bands + (size_t)(r * 2) * T_LEN;
        acc0 = fmaf(bb[t], g, acc0);
        acc1 = fmaf(bb[T_LEN + t], g, acc1);
    }
    comb[(size_t)(b * 2) * T_LEN + t] = acc0;
    comb[(size_t)(b * 2 + 1) * T_LEN + t] = acc1;
}

// ---------------- conv0: 2->64, k3 d1, + GELU ------------------------------
__global__ void __launch_bounds__(256) conv0_kernel(
    const float* __restrict__ comb, const float* __restrict__ w0,
    const float* __restrict__ b0, float* __restrict__ out)
{
    __shared__ float sx[2][66];
    __shared__ float sw[384];
    const int b = blockIdx.y;
    const int t0 = blockIdx.x * 64;
    const int tid = threadIdx.x;
    for (int i = tid; i < 384; i += 256) sw[i] = w0[i];
    for (int i = tid; i < 132; i += 256) {
        int c = i / 66, col = i - c * 66;
        int g = t0 - 1 + col;
        sx[c][col] = (g >= 0 && g < T_LEN) ? comb[(size_t)(b * 2 + c) * T_LEN + g] : 0.0f;
    }
    __syncthreads();
    const int tx = tid & 63, ty = tid >> 6;   // ty: 4 groups x 16 oc
    const int t = t0 + tx;
    float xv[2][3];
    #pragma unroll
    for (int c = 0; c < 2; c++)
        #pragma unroll
        for (int k = 0; k < 3; k++) xv[c][k] = sx[c][tx + k];
    #pragma unroll
    for (int j = 0; j < 16; j++) {
        int oc = ty * 16 + j;
        float a = __ldg(&b0[oc]);
        const float* w = &sw[oc * 6];
        #pragma unroll
        for (int c = 0; c < 2; c++)
            #pragma unroll
            for (int k = 0; k < 3; k++) a = fmaf(w[c * 3 + k], xv[c][k], a);
        if (t < T_LEN) out[((size_t)(b * 64 + oc)) * T_LEN + t] = gelu_exact(a);
    }
}

// ---------------- weight transpose for 64x64 convs: [oc][ic][k]->[ic][k][oc]
__global__ void prep_w_kernel(const float* __restrict__ w1, const float* __restrict__ w2,
                              const float* __restrict__ w3, float* __restrict__ wt)
{
    int i = blockIdx.x * 256 + threadIdx.x;
    if (i >= 3 * 12288) return;
    int l = i / 12288, j = i - l * 12288;
    int oc = j & 63, r = j >> 6;
    int k = r % 3, ic = r / 3;
    const float* src = (l == 0) ? w1 : (l == 1) ? w2 : w3;
    wt[i] = src[oc * 192 + ic * 3 + k];
}

// ---------------- conv64: 64->64, k3, dilation D, + GELU -------------------
// Weights read via warp-uniform __ldg float4 (L1-resident, 48KB); only the
// input tile lives in dynamic smem (<= 36.9KB) -> no smem opt-in needed,
// ~3 CTAs/SM occupancy.
template <int D>
__global__ void __launch_bounds__(256) conv64_kernel(
    const float* __restrict__ in, const float* __restrict__ wT,
    const float* __restrict__ bias, float* __restrict__ out)
{
    constexpr int PADT = 128 + 2 * D + ((2 * D) % 4 ? (4 - (2 * D) % 4) : 0); // mult of 4
    extern __shared__ float sx[];      // 64 * PADT
    const int b = blockIdx.y;
    const int t0 = blockIdx.x * 128;
    const int tid = threadIdx.x;

    const float* inb = in + (size_t)b * 64 * T_LEN;
    for (int i = tid; i < 64 * PADT; i += 256) {
        int ic = i / PADT, col = i - ic * PADT;
        int g = t0 - D + col;
        sx[i] = (g >= 0 && g < T_LEN) ? inb[(size_t)ic * T_LEN + g] : 0.0f;
    }
    __syncthreads();

    const int tx = tid & 31, ty = tid >> 5;
    const int ocb = ty * 8;
    const int p = tx * 4;

    float acc[8][4];
    #pragma unroll
    for (int j = 0; j < 8; j++) {
        float bv = __ldg(&bias[ocb + j]);
        #pragma unroll
        for (int q = 0; q < 4; q++) acc[j][q] = bv;
    }

    for (int ic = 0; ic < 64; ic++) {
        const float* xr = sx + ic * PADT + p;
        float xw[3][4];
        if (D == 2) {
            float4 a = *(const float4*)xr;
            float4 c2 = *(const float4*)(xr + 4);
            xw[0][0] = a.x;  xw[0][1] = a.y;  xw[0][2] = a.z;  xw[0][3] = a.w;
            xw[1][0] = a.z;  xw[1][1] = a.w;  xw[1][2] = c2.x; xw[1][3] = c2.y;
            xw[2][0] = c2.x; xw[2][1] = c2.y; xw[2][2] = c2.z; xw[2][3] = c2.w;
        } else {
            float4 a = *(const float4*)xr;
            float4 bb = *(const float4*)(xr + D);
            float4 cc = *(const float4*)(xr + 2 * D);
            xw[0][0] = a.x;  xw[0][1] = a.y;  xw[0][2] = a.z;  xw[0][3] = a.w;
            xw[1][0] = bb.x; xw[1][1] = bb.y; xw[1][2] = bb.z; xw[1][3] = bb.w;
            xw[2][0] = cc.x; xw[2][1] = cc.y; xw[2][2] = cc.z; xw[2][3] = cc.w;
        }
        const float* wb = wT + ic * 192 + ocb;   // warp-uniform global loads
        #pragma unroll
        for (int k = 0; k < 3; k++) {
            float4 wA = __ldg((const float4*)(wb + k * 64));
            float4 wB = __ldg((const float4*)(wb + k * 64 + 4));
            float wv[8] = {wA.x, wA.y, wA.z, wA.w, wB.x, wB.y, wB.z, wB.w};
            #pragma unroll
            for (int j = 0; j < 8; j++)
                #pragma unroll
                for (int q = 0; q < 4; q++)
                    acc[j][q] = fmaf(wv[j], xw[k][q], acc[j][q]);
        }
    }

    const int tb = t0 + p;
    float* outb = out + ((size_t)(b * 64 + ocb)) * T_LEN;
    #pragma unroll
    for (int j = 0; j < 8; j++) {
        if (tb + 3 < T_LEN) {
            float4 o;
            o.x = gelu_exact(acc[j][0]); o.y = gelu_exact(acc[j][1]);
            o.z = gelu_exact(acc[j][2]); o.w = gelu_exact(acc[j][3]);
            *(float4*)(outb + (size_t)j * T_LEN + tb) = o;
        } else {
            #pragma unroll
            for (int q = 0; q < 4; q++)
                if (tb + q < T_LEN) outb[(size_t)j * T_LEN + tb + q] = gelu_exact(acc[j][q]);
        }
    }
}

// ---------------- conv4 (64->2, k3 d1) + final dry/wet mix -----------------
__global__ void __launch_bounds__(128) conv4_kernel(
    const float* __restrict__ in, const float* __restrict__ w4,
    const float* __restrict__ b4, const float* __restrict__ comb,
    const float* __restrict__ audio, const float* __restrict__ params,
    float* __restrict__ outp)
{
    __shared__ float sx[64 * 130];
    __shared__ float sw[384];
    const int b = blockIdx.y;
    const int t0 = blockIdx.x * 128;
    const int tid = threadIdx.x;
    for (int i = tid; i < 384; i += 128) sw[i] = w4[i];
    const float* inb = in + (size_t)b * 64 * T_LEN;
    for (int i = tid; i < 64 * 130; i += 128) {
        int ic = i / 130, col = i - ic * 130;
        int g = t0 - 1 + col;
        sx[i] = (g >= 0 && g < T_LEN) ? inb[(size_t)ic * T_LEN + g] : 0.0f;
    }
    __syncthreads();
    const int t = t0 + tid;
    float acc0 = __ldg(&b4[0]);
    float acc1 = __ldg(&b4[1]);
    #pragma unroll 8
    for (int ic = 0; ic < 64; ic++) {
        float x0 = sx[ic * 130 + tid];
        float x1 = sx[ic * 130 + tid + 1];
        float x2 = sx[ic * 130 + tid + 2];
        const float* wa = &sw[ic * 3];
        const float* wc = &sw[192 + ic * 3];
        acc0 = fmaf(wa[0], x0, fmaf(wa[1], x1, fmaf(wa[2], x2, acc0)));
        acc1 = fmaf(wc[0], x0, fmaf(wc[1], x1, fmaf(wc[2], x2, acc1)));
    }
    if (t < T_LEN) {
        float amt = __ldg(&params[b * 7]);
        size_t i0 = (size_t)(b * 2) * T_LEN + t;
        size_t i1 = (size_t)(b * 2 + 1) * T_LEN + t;
        outp[i0] = (1.0f - amt) * audio[i0] + amt * (comb[i0] + acc0);
        outp[i1] = (1.0f - amt) * audio[i1] + amt * (comb[i1] + acc1);
    }
}

// ---------------------------------------------------------------------------
extern "C" void kernel_launch(void* const* d_in, const int* in_sizes, int n_in,
                              void* d_out, int out_size)
{
    (void)in_sizes; (void)n_in; (void)out_size;
    const float* audio     = (const float*)d_in[0];
    const float* params    = (const float*)d_in[1];
    const float* rel       = (const float*)d_in[2];
    const float* knee_db   = (const float*)d_in[3];
    const float* ir_low_lp = (const float*)d_in[4];
    const float* ir_low_hp = (const float*)d_in[5];
    const float* ir_hi_lp  = (const float*)d_in[6];
    const float* ir_hi_hp  = (const float*)d_in[7];
    const float* w0 = (const float*)d_in[8];   const float* b0 = (const float*)d_in[9];
    const float* w1 = (const float*)d_in[10];  const float* b1 = (const float*)d_in[11];
    const float* w2 = (const float*)d_in[12];  const float* b2 = (const float*)d_in[13];
    const float* w3 = (const float*)d_in[14];  const float* b3 = (const float*)d_in[15];
    const float* w4 = (const float*)d_in[16];  const float* b4 = (const float*)d_in[17];
    float* out = (float*)d_out;

    float *bands, *mh, *xrms, *env, *comb, *a0, *a1, *wt;
    cudaGetSymbolAddress((void**)&bands, g_bands);
    cudaGetSymbolAddress((void**)&mh,    g_mh);
    cudaGetSymbolAddress((void**)&xrms,  g_xrms);
    cudaGetSymbolAddress((void**)&env,   g_env);
    cudaGetSymbolAddress((void**)&comb,  g_comb);
    cudaGetSymbolAddress((void**)&a0,    g_act0);
    cudaGetSymbolAddress((void**)&a1,    g_act1);
    cudaGetSymbolAddress((void**)&wt,    g_wt);

    // dynamic smem sizes for conv64 variants (input tile only; all <= 48KB)
    const int smem2 = 64 * 132 * 4;
    const int smem4 = 64 * 136 * 4;
    const int smem8 = 64 * 144 * 4;

    // 1) crossover FIRs
    fir_kernel<1><<<dim3(87, 16), 256>>>(audio, ir_low_lp, ir_low_hp, bands, mh);
    fir_kernel<2><<<dim3(87, 16), 256>>>(nullptr, ir_hi_lp, ir_hi_hp, bands, mh);

    // 2) envelope + gains + combine
    xrms_kernel<<<dim3(24, (TC + 7) / 8), 256>>>(bands, xrms);
    env_kernel<<<1, 32>>>(xrms, rel, env);
    combine_kernel<<<dim3((T_LEN + 255) / 256, NB), 256>>>(bands, env, params, knee_db, comb);

    // 3) TCN
    prep_w_kernel<<<(3 * 12288 + 255) / 256, 256>>>(w1, w2, w3, wt);
    conv0_kernel<<<dim3((T_LEN + 63) / 64, NB), 256>>>(comb, w0, b0, a0);
    conv64_kernel<2><<<dim3((T_LEN + 127) / 128, NB), 256, smem2>>>(a0, wt,           b1, a1);
    conv64_kernel<4><<<dim3((T_LEN + 127) / 128, NB), 256, smem4>>>(a1, wt + 12288,   b2, a0);
    conv64_kernel<8><<<dim3((T_LEN + 127) / 128, NB), 256, smem8>>>(a0, wt + 24576,   b3, a1);

    // 4) final conv + mix
    conv4_kernel<<<dim3((T_LEN + 127) / 128, NB), 128>>>(a1, w4, b4, comb, audio, params, out);
}

// round 10
// speedup vs baseline: 3.7632x; 3.7632x over previous
#include <cuda_runtime.h>
#include <cuda_bf16.h>
#include <math.h>
#include <stdint.h>

#define T_LEN 88200
#define NB 8
#define TC 1378
#define IN_GAIN 1.8197008586099834f
#define ABOVE_SLOPE 0.98500749625187401f
#define BELOW_SLOPE 0.76019184652277820f

// ---------------- scratch ----------------
__device__ float g_mh[NB * 2 * T_LEN];
__device__ float g_bands[NB * 3 * 2 * T_LEN];   // [b][band][c][t] band0=high,1=mid,2=low
__device__ float g_xrms[24 * TC];
__device__ float g_env[24 * TC];
__device__ float g_comb[NB * 2 * T_LEN];
__device__ __nv_bfloat16 g_bA[(size_t)NB * T_LEN * 64];   // activations [b][t][64] bf16
__device__ __nv_bfloat16 g_bB[(size_t)NB * T_LEN * 64];
__device__ __nv_bfloat16 g_wtb[3 * 3 * 64 * 64];          // weights [layer][tap][oc][ic] bf16
__device__ float g_w0p[64 * 8];                 // conv0 weights packed [oc][w0..w5,bias,0]
__device__ float g_w4p[3 * 32 * 4];             // conv4 weights packed [k][icpair][4]

// ---------------- helpers ----------------
__device__ __forceinline__ uint32_t s2u(const void* p) {
    uint32_t a;
    asm("{ .reg .u64 t; cvta.to.shared.u64 t, %1; cvt.u32.u64 %0, t; }" : "=r"(a) : "l"(p));
    return a;
}
__device__ __forceinline__ float gelu_tanh(float x) {
    float u = 0.7978845608028654f * fmaf(0.044715f * x, x * x, x);
    float t; asm("tanh.approx.f32 %0, %1;" : "=f"(t) : "f"(u));
    return 0.5f * x * (1.0f + t);
}
__device__ __forceinline__ uint32_t pack_bf16(float lo, float hi) {
    uint32_t r;
    asm("cvt.rn.satfinite.bf16x2.f32 %0, %1, %2;" : "=r"(r) : "f"(hi), "f"(lo));
    return r;
}
__device__ __forceinline__ float knee_fn(float x, float thr, float slope, float k) {
    float diff = x - thr, kh = 0.5f * k;
    if (fabsf(diff) <= kh) { float u = diff + kh; return slope * u * u / (2.0f * k); }
    return diff > kh ? slope * diff : 0.0f;
}

// ---------------- prep kernels ----------------
__global__ void prep_wtb_kernel(const float* __restrict__ w1, const float* __restrict__ w2,
                                const float* __restrict__ w3, __nv_bfloat16* __restrict__ wtb)
{
    int i = blockIdx.x * 256 + threadIdx.x;
    if (i >= 3 * 12288) return;
    int l = i / 12288, j = i - l * 12288;
    int tap = j >> 12, e = j & 4095;
    int oc = e >> 6, ic = e & 63;
    const float* src = (l == 0) ? w1 : (l == 1) ? w2 : w3;
    wtb[i] = __float2bfloat16(src[oc * 192 + ic * 3 + tap]);
}

__global__ void prep_small_kernel(const float* __restrict__ w0, const float* __restrict__ b0,
                                  const float* __restrict__ w4,
                                  float* __restrict__ w0p, float* __restrict__ w4p)
{
    int i = threadIdx.x;
    if (i < 64) {
        #pragma unroll
        for (int q = 0; q < 6; q++) w0p[i * 8 + q] = w0[i * 6 + q];
        w0p[i * 8 + 6] = b0[i];
        w0p[i * 8 + 7] = 0.0f;
    }
    if (i < 96) {   // (k, icpair)
        int k = i / 32, jp = i % 32;
        w4p[i * 4 + 0] = w4[(2 * jp) * 3 + k];
        w4p[i * 4 + 1] = w4[(2 * jp + 1) * 3 + k];
        w4p[i * 4 + 2] = w4[192 + (2 * jp) * 3 + k];
        w4p[i * 4 + 3] = w4[192 + (2 * jp + 1) * 3 + k];
    }
}

// ---------------- FIR crossover: 8 t/thread rolling window -----------------
template <int STAGE>
__global__ void __launch_bounds__(256) fir_kernel(
    const float* __restrict__ in, const float* __restrict__ wA,
    const float* __restrict__ wB, float* __restrict__ bands, float* __restrict__ mh)
{
    __shared__ __align__(16) float swa[512], swb[512], sx[2560];
    const int row = blockIdx.y, b = row >> 1, c = row & 1;
    const int t0 = blockIdx.x * 2048;
    const int tid = threadIdx.x;

    for (int i = tid; i < 512; i += 256) { swa[i] = wA[i]; swb[i] = wB[i]; }
    const float gain = (STAGE == 1) ? IN_GAIN : 1.0f;
    const float* xin = (STAGE == 1) ? (in + row * T_LEN) : (mh + row * T_LEN);
    for (int i = tid; i < 2559; i += 256) {
        int g = t0 - 511 + i;
        sx[i] = (g >= 0 && g < T_LEN) ? xin[g] * gain : 0.0f;
    }
    __syncthreads();

    float aA[8] = {0,0,0,0,0,0,0,0}, aB[8] = {0,0,0,0,0,0,0,0};
    const int base = tid * 8;
    for (int k0 = 0; k0 < 512; k0 += 8) {
        float xw[16];
        const float4* p = (const float4*)&sx[base + k0];
        float4 v0 = p[0], v1 = p[1], v2 = p[2], v3 = p[3];
        xw[0]=v0.x; xw[1]=v0.y; xw[2]=v0.z; xw[3]=v0.w;
        xw[4]=v1.x; xw[5]=v1.y; xw[6]=v1.z; xw[7]=v1.w;
        xw[8]=v2.x; xw[9]=v2.y; xw[10]=v2.z; xw[11]=v2.w;
        xw[12]=v3.x; xw[13]=v3.y; xw[14]=v3.z; xw[15]=v3.w;
        #pragma unroll
        for (int kk = 0; kk < 8; kk++) {
            float wa = swa[k0 + kk], wb = swb[k0 + kk];
            #pragma unroll
            for (int j = 0; j < 8; j++) {
                float v = xw[kk + j];
                aA[j] = fmaf(wa, v, aA[j]);
                aB[j] = fmaf(wb, v, aB[j]);
            }
        }
    }

    float* outA;
    float* outB;
    if (STAGE == 1) {
        outA = bands + ((size_t)(b * 3 + 2) * 2 + c) * T_LEN;
        outB = mh + (size_t)row * T_LEN;
    } else {
        outA = bands + ((size_t)(b * 3 + 1) * 2 + c) * T_LEN;
        outB = bands + ((size_t)(b * 3 + 0) * 2 + c) * T_LEN;
    }
    #pragma unroll
    for (int j = 0; j < 8; j++) {
        int t = t0 + base + j;
        if (t < T_LEN) { outA[t] = aA[j]; outB[t] = aB[j]; }
    }
}

// ---------------- per-band RMS ----------------
__global__ void xrms_kernel(const float* __restrict__ bands, float* __restrict__ xrms)
{
    const int row = blockIdx.x;
    const int warp = threadIdx.x >> 5, lane = threadIdx.x & 31;
    const int j = blockIdx.y * 8 + warp;
    if (j >= TC) return;
    const float* p0 = bands + (size_t)row * 2 * T_LEN;
    const float* p1 = p0 + T_LEN;
    int base = j * 64;
    float v0 = p0[base + lane], v1 = p0[base + lane + 32];
    float u0 = p1[base + lane], u1 = p1[base + lane + 32];
    float s = v0*v0 + v1*v1 + u0*u0 + u1*u1;
    #pragma unroll
    for (int o = 16; o > 0; o >>= 1) s += __shfl_xor_sync(0xffffffffu, s, o);
    if (lane == 0) xrms[row * TC + j] = sqrtf(s * (1.0f / 128.0f) + 1e-7f);
}

// ---------------- release envelope: parallel max-scan ----------------
// e[n] = max(x[n], k*e[n-1]) == cummax(x[n]*k^-n)*k^n
__global__ void __launch_bounds__(256) envscan_kernel(
    const float* __restrict__ xrms, const float* __restrict__ rel_alphas,
    float* __restrict__ env)
{
    __shared__ float wtot[8];
    const int r = blockIdx.x;
    const int tid = threadIdx.x, lane = tid & 31, warp = tid >> 5;
    float kk = 1.0f - rel_alphas[r >> 3];   // reference repeat quirk: rel[r/8]
    float lg = log2f(kk);                    // negative
    const float* x = xrms + r * TC;

    float loc[6];
    float run = 0.0f;
    #pragma unroll
    for (int i = 0; i < 6; i++) {
        int n = tid * 6 + i;
        float z = (n < TC) ? x[n] * exp2f(-lg * (float)n) : 0.0f;
        run = fmaxf(run, z);
        loc[i] = run;
    }
    float inc = run;
    #pragma unroll
    for (int o = 1; o < 32; o <<= 1) {
        float v = __shfl_up_sync(0xffffffffu, inc, o);
        if (lane >= o) inc = fmaxf(inc, v);
    }
    float excl_in_warp = __shfl_up_sync(0xffffffffu, inc, 1);
    if (lane == 0) excl_in_warp = 0.0f;
    if (lane == 31) wtot[warp] = inc;
    __syncthreads();
    float wpre = 0.0f;
    #pragma unroll
    for (int w = 0; w < 8; w++) if (w < warp) wpre = fmaxf(wpre, wtot[w]);
    float E = fmaxf(wpre, excl_in_warp);

    #pragma unroll
    for (int i = 0; i < 6; i++) {
        int n = tid * 6 + i;
        if (n < TC) {
            float ez = fmaxf(E, loc[i]);
            env[r * TC + n] = ez * exp2f(lg * (float)n);
        }
    }
}

// ---------------- gain + band combine ----------------
__global__ void combine_kernel(const float* __restrict__ bands, const float* __restrict__ env,
                               const float* __restrict__ params, const float* __restrict__ knee_db,
                               float* __restrict__ comb)
{
    const int t = blockIdx.x * 256 + threadIdx.x;
    const int b = blockIdx.y;
    if (t >= T_LEN) return;
    const float* pp = params + b * 7;
    const float knee = *knee_db;

    float pos = (float)t * (1377.0f / 88199.0f);
    int i0 = (int)floorf(pos);
    if (i0 > TC - 2) i0 = TC - 2;
    if (i0 < 0) i0 = 0;
    float frac = pos - (float)i0;

    float acc0 = 0.f, acc1 = 0.f;
    #pragma unroll
    for (int band = 0; band < 3; band++) {
        int r = b * 3 + band;
        float e0 = env[r * TC + i0], e1 = env[r * TC + i0 + 1];
        float e = e0 * (1.0f - frac) + e1 * frac;
        float edb = 20.0f * log10f(e + 1e-7f);
        float ta = pp[3 - band], tb = pp[6 - band];
        float sa = (band == 0) ? 1.0f : ABOVE_SLOPE;
        float gdb = -knee_fn(edb, ta, sa, knee) + knee_fn(-edb, -tb, BELOW_SLOPE, knee);
        float og = (band == 1) ? 5.7f : 10.3f;
        float v = fminf(fmaxf(gdb + og, -80.0f), 40.0f);
        float g = exp10f(v * 0.05f);
        const float* bb = bands + (size_t)(r * 2) * T_LEN;
        acc0 = fmaf(bb[t], g, acc0);
        acc1 = fmaf(bb[T_LEN + t], g, acc1);
    }
    comb[(size_t)(b * 2) * T_LEN + t] = acc0;
    comb[(size_t)(b * 2 + 1) * T_LEN + t] = acc1;
}

// ---------------- conv0: 2->64, k3 d1, gelu, writes bf16 [b][t][64] --------
__global__ void __launch_bounds__(256) conv0_kernel(
    const float* __restrict__ comb, const float* __restrict__ w0p,
    __nv_bfloat16* __restrict__ out)
{
    __shared__ float4 sw[128];
    const int b = blockIdx.y;
    const int t = blockIdx.x * 256 + threadIdx.x;
    for (int i = threadIdx.x; i < 128; i += 256) sw[i] = ((const float4*)w0p)[i];
    __syncthreads();
    if (t >= T_LEN) return;

    float xv[6];
    const float* c0 = comb + (size_t)(b * 2) * T_LEN;
    const float* c1 = c0 + T_LEN;
    #pragma unroll
    for (int k = 0; k < 3; k++) {
        int g = t - 1 + k;
        bool ok = (g >= 0 && g < T_LEN);
        xv[k]     = ok ? c0[g] : 0.0f;
        xv[3 + k] = ok ? c1[g] : 0.0f;
    }
    uint32_t r[32];
    #pragma unroll
    for (int p = 0; p < 32; p++) {
        float4 wA0 = sw[(2*p)*2], wB0 = sw[(2*p)*2 + 1];
        float4 wA1 = sw[(2*p+1)*2], wB1 = sw[(2*p+1)*2 + 1];
        float a0 = wB0.z, a1 = wB1.z;
        a0 = fmaf(wA0.x, xv[0], a0); a0 = fmaf(wA0.y, xv[1], a0); a0 = fmaf(wA0.z, xv[2], a0);
        a0 = fmaf(wA0.w, xv[3], a0); a0 = fmaf(wB0.x, xv[4], a0); a0 = fmaf(wB0.y, xv[5], a0);
        a1 = fmaf(wA1.x, xv[0], a1); a1 = fmaf(wA1.y, xv[1], a1); a1 = fmaf(wA1.z, xv[2], a1);
        a1 = fmaf(wA1.w, xv[3], a1); a1 = fmaf(wB1.x, xv[4], a1); a1 = fmaf(wB1.y, xv[5], a1);
        r[p] = pack_bf16(gelu_tanh(a0), gelu_tanh(a1));
    }
    uint4* dst = (uint4*)(out + ((size_t)b * T_LEN + t) * 64);
    #pragma unroll
    for (int q = 0; q < 8; q++) dst[q] = ((uint4*)r)[q];
}

// ---------------- conv64 via mma.sync bf16 (legacy HMMA path) --------------
// D[128t x 64oc] = sum_{tap,ic} A[t+(tap-1)*Dil, ic] * W[tap][oc][ic]
// Block: 256 thr (8 warps); warp w owns t-rows [w*16, w*16+16) x all 64 oc.
// A: one smem buffer of (128+2*Dil) rows x 72 bf16 (144B stride, conflict-free
// ldmatrix); taps index shifted rows. B: [tap][oc][ic] 144B stride.
template <int DIL>
__global__ void __launch_bounds__(256) conv64_mma(
    const __nv_bfloat16* __restrict__ in,   // [b][t][64]
    const __nv_bfloat16* __restrict__ wtb,  // [tap][oc][ic] bf16
    const float* __restrict__ bias,
    __nv_bfloat16* __restrict__ out)
{
    constexpr int AROWS = 128 + 2 * DIL;
    extern __shared__ __align__(16) char sm[];
    char* sA = sm;                         // AROWS x 144B
    char* sB = sm + AROWS * 144;           // 192 x 144B
    __shared__ float sbias[64];

    const int b = blockIdx.y;
    const int t0 = blockIdx.x * 128;
    const int tid = threadIdx.x, lane = tid & 31, warp = tid >> 5;

    if (tid < 64) sbias[tid] = bias[tid];

    for (int i = tid; i < 1536; i += 256) {          // B: 192 rows x 8 chunks
        int row = i >> 3, ch = i & 7;
        *(uint4*)(sB + row * 144 + ch * 16) = ((const uint4*)wtb)[i];
    }
    for (int i = tid; i < AROWS * 8; i += 256) {     // A
        int row = i >> 3, ch = i & 7;
        int g = t0 - DIL + row;
        uint4 v = make_uint4(0u, 0u, 0u, 0u);
        if (g >= 0 && g < T_LEN)
            v = *(const uint4*)(in + ((size_t)b * T_LEN + g) * 64 + ch * 8);
        *(uint4*)(sA + row * 144 + ch * 16) = v;
    }
    __syncthreads();

    const uint32_t sAu = s2u(sA), sBu = s2u(sB);
    float acc[8][4];
    #pragma unroll
    for (int nt = 0; nt < 8; nt++)
        #pragma unroll
        for (int q = 0; q < 4; q++) acc[nt][q] = 0.0f;

    const int mrow = warp * 16;
    // ldmatrix per-thread source row/col within the m16k16 tile
    const int lrow = (lane & 7) + ((lane >> 3) & 1) * 8;
    const int lcol = (lane >> 4) * 16;
    const int bro = (lane >> 2) * 144 + (lane & 3) * 4;   // B frag base (n, k0)

    #pragma unroll
    for (int tap = 0; tap < 3; tap++) {
        const uint32_t abase = sAu + (uint32_t)((mrow + tap * DIL + lrow) * 144 + lcol);
        const uint32_t bbase = sBu + (uint32_t)(tap * 64 * 144 + bro);
        #pragma unroll
        for (int kc = 0; kc < 4; kc++) {
            uint32_t a0, a1, a2, a3;
            asm volatile("ldmatrix.sync.aligned.m8n8.x4.shared.b16 {%0,%1,%2,%3}, [%4];"
                : "=r"(a0), "=r"(a1), "=r"(a2), "=r"(a3) : "r"(abase + kc * 32));
            #pragma unroll
            for (int nt = 0; nt < 8; nt++) {
                uint32_t bad = bbase + nt * 8 * 144 + kc * 32;
                uint32_t b0, b1;
                asm volatile("ld.shared.b32 %0, [%1];" : "=r"(b0) : "r"(bad));
                asm volatile("ld.shared.b32 %0, [%1];" : "=r"(b1) : "r"(bad + 16));
                asm volatile("mma.sync.aligned.m16n8k16.row.col.f32.bf16.bf16.f32 "
                    "{%0,%1,%2,%3}, {%4,%5,%6,%7}, {%8,%9}, {%0,%1,%2,%3};"
                    : "+f"(acc[nt][0]), "+f"(acc[nt][1]), "+f"(acc[nt][2]), "+f"(acc[nt][3])
                    : "r"(a0), "r"(a1), "r"(a2), "r"(a3), "r"(b0), "r"(b1));
            }
        }
    }

    // epilogue: c0,c1 -> (row=lane/4, col=(lane%4)*2); c2,c3 -> row+8
    const int r1 = mrow + (lane >> 2);
    const int c0 = (lane & 3) * 2;
    const int t1 = t0 + r1, t2 = t1 + 8;
    __nv_bfloat16* ob = out + (size_t)b * T_LEN * 64;
    #pragma unroll
    for (int nt = 0; nt < 8; nt++) {
        int col = nt * 8 + c0;
        float bv0 = sbias[col], bv1 = sbias[col + 1];
        if (t1 < T_LEN) {
            uint32_t pk = pack_bf16(gelu_tanh(acc[nt][0] + bv0), gelu_tanh(acc[nt][1] + bv1));
            *(uint32_t*)(ob + (size_t)t1 * 64 + col) = pk;
        }
        if (t2 < T_LEN) {
            uint32_t pk = pack_bf16(gelu_tanh(acc[nt][2] + bv0), gelu_tanh(acc[nt][3] + bv1));
            *(uint32_t*)(ob + (size_t)t2 * 64 + col) = pk;
        }
    }
}

// ---------------- conv4 (64->2, k3 d1) + dry/wet mix -----------------------
__global__ void __launch_bounds__(128) conv4_kernel(
    const __nv_bfloat16* __restrict__ in, const float* __restrict__ w4p,
    const float* __restrict__ b4, const float* __restrict__ comb,
    const float* __restrict__ audio, const float* __restrict__ params,
    float* __restrict__ outp)
{
    __shared__ uint32_t sxw[130 * 32];
    __shared__ float4 sw4p[96];
    const int b = blockIdx.y;
    const int t0 = blockIdx.x * 128;
    const int tid = threadIdx.x, lane = tid & 31;

    for (int i = tid; i < 96; i += 128) sw4p[i] = ((const float4*)w4p)[i];
    for (int i = tid; i < 130 * 8; i += 128) {
        int row = i >> 3, ch = i & 7;
        int g = t0 - 1 + row;
        uint4 v = make_uint4(0u, 0u, 0u, 0u);
        if (g >= 0 && g < T_LEN)
            v = *(const uint4*)(in + ((size_t)b * T_LEN + g) * 64 + ch * 8);
        ((uint4*)sxw)[i] = v;
    }
    __syncthreads();

    const int t = t0 + tid;
    float a0 = __ldg(&b4[0]), a1 = __ldg(&b4[1]);
    #pragma unroll
    for (int k = 0; k < 3; k++) {
        const uint32_t* xr = &sxw[(tid + k) * 32];
        #pragma unroll 8
        for (int jj = 0; jj < 32; jj++) {
            int j = (jj + lane) & 31;
            uint32_t xp = xr[j];
            float2 xv = __bfloat1622float2(*(const __nv_bfloat162*)&xp);
            float4 w = sw4p[k * 32 + j];
            a0 = fmaf(w.x, xv.x, fmaf(w.y, xv.y, a0));
            a1 = fmaf(w.z, xv.x, fmaf(w.w, xv.y, a1));
        }
    }
    if (t < T_LEN) {
        float amt = __ldg(&params[b * 7]);
        size_t i0 = (size_t)(b * 2) * T_LEN + t;
        size_t i1 = (size_t)(b * 2 + 1) * T_LEN + t;
        outp[i0] = (1.0f - amt) * audio[i0] + amt * (comb[i0] + a0);
        outp[i1] = (1.0f - amt) * audio[i1] + amt * (comb[i1] + a1);
    }
}

// ---------------------------------------------------------------------------
extern "C" void kernel_launch(void* const* d_in, const int* in_sizes, int n_in,
                              void* d_out, int out_size)
{
    (void)in_sizes; (void)n_in; (void)out_size;
    const float* audio     = (const float*)d_in[0];
    const float* params    = (const float*)d_in[1];
    const float* rel       = (const float*)d_in[2];
    const float* knee_db   = (const float*)d_in[3];
    const float* ir_low_lp = (const float*)d_in[4];
    const float* ir_low_hp = (const float*)d_in[5];
    const float* ir_hi_lp  = (const float*)d_in[6];
    const float* ir_hi_hp  = (const float*)d_in[7];
    const float* w0 = (const float*)d_in[8];
    const float* b0 = (const float*)d_in[9];
    const float* w1 = (const float*)d_in[10];  const float* b1 = (const float*)d_in[11];
    const float* w2 = (const float*)d_in[12];  const float* b2 = (const float*)d_in[13];
    const float* w3 = (const float*)d_in[14];  const float* b3 = (const float*)d_in[15];
    const float* w4 = (const float*)d_in[16];  const float* b4 = (const float*)d_in[17];
    float* out = (float*)d_out;

    float *bands, *mh, *xrms, *env, *comb, *w0p, *w4p;
    __nv_bfloat16 *bA, *bB, *wtb;
    cudaGetSymbolAddress((void**)&bands, g_bands);
    cudaGetSymbolAddress((void**)&mh,    g_mh);
    cudaGetSymbolAddress((void**)&xrms,  g_xrms);
    cudaGetSymbolAddress((void**)&env,   g_env);
    cudaGetSymbolAddress((void**)&comb,  g_comb);
    cudaGetSymbolAddress((void**)&bA,    g_bA);
    cudaGetSymbolAddress((void**)&bB,    g_bB);
    cudaGetSymbolAddress((void**)&wtb,   g_wtb);
    cudaGetSymbolAddress((void**)&w0p,   g_w0p);
    cudaGetSymbolAddress((void**)&w4p,   g_w4p);

    // dynamic smem: A rows x 144B + B 192 x 144B  (all < 48KB, no opt-in)
    const int smem2 = (128 + 4)  * 144 + 192 * 144;   // 46656
    const int smem4 = (128 + 8)  * 144 + 192 * 144;   // 47232
    const int smem8 = (128 + 16) * 144 + 192 * 144;   // 48384

    // prep (independent)
    prep_wtb_kernel<<<(3 * 12288 + 255) / 256, 256>>>(w1, w2, w3, wtb);
    prep_small_kernel<<<1, 128>>>(w0, b0, w4, w0p, w4p);

    // crossover FIRs
    fir_kernel<1><<<dim3(44, 16), 256>>>(audio, ir_low_lp, ir_low_hp, bands, mh);
    fir_kernel<2><<<dim3(44, 16), 256>>>(nullptr, ir_hi_lp, ir_hi_hp, bands, mh);

    // envelope + combine
    xrms_kernel<<<dim3(24, (TC + 7) / 8), 256>>>(bands, xrms);
    envscan_kernel<<<24, 256>>>(xrms, rel, env);
    combine_kernel<<<dim3((T_LEN + 255) / 256, NB), 256>>>(bands, env, params, knee_db, comb);

    // TCN
    conv0_kernel<<<dim3((T_LEN + 255) / 256, NB), 256>>>(comb, w0p, bA);
    conv64_mma<2><<<dim3((T_LEN + 127) / 128, NB), 256, smem2>>>(bA, wtb,          b1, bB);
    conv64_mma<4><<<dim3((T_LEN + 127) / 128, NB), 256, smem4>>>(bB, wtb + 12288,  b2, bA);
    conv64_mma<8><<<dim3((T_LEN + 127) / 128, NB), 256, smem8>>>(bA, wtb + 24576,  b3, bB);

    // final conv + mix
    conv4_kernel<<<dim3((T_LEN + 127) / 128, NB), 128>>>(bB, w4p, b4, comb, audio, params, out);
}